// round 14
// baseline (speedup 1.0000x reference)
#include <cuda_runtime.h>
#include <cuda_bf16.h>

// Problem shapes (fixed by the dataset)
#define BB   16384
#define CC   10
#define KK   8
#define DIM  128

#define WARPS_PER_BLOCK 8
#define NBLK (BB / WARPS_PER_BLOCK)   // 2048
#define NP2  16

// Scratch (device globals: allocation-guard-safe)
__device__ float  g_part[NBLK];
__device__ double g_p2[NP2];

// 256-bit table load with L2 evict_last (sm_103 requires v8.b32 for the hint).
// Both tables (102 MB) fit in 126 MB L2 and L2 persists across graph replays;
// bias replacement so table rows survive replay-to-replay.
struct F8 { float v[8]; };
__device__ __forceinline__ F8 ldg256_persist(const void* p) {
    unsigned r0,r1,r2,r3,r4,r5,r6,r7;
    asm volatile("ld.global.nc.L2::evict_last.v8.b32 {%0,%1,%2,%3,%4,%5,%6,%7}, [%8];"
                 : "=r"(r0),"=r"(r1),"=r"(r2),"=r"(r3),
                   "=r"(r4),"=r"(r5),"=r"(r6),"=r"(r7) : "l"(p));
    F8 f;
    f.v[0]=__uint_as_float(r0); f.v[1]=__uint_as_float(r1);
    f.v[2]=__uint_as_float(r2); f.v[3]=__uint_as_float(r3);
    f.v[4]=__uint_as_float(r4); f.v[5]=__uint_as_float(r5);
    f.v[6]=__uint_as_float(r6); f.v[7]=__uint_as_float(r7);
    return f;
}

// Stage 1: one WARP per example. Rows are fetched as 32B chunks with 256-bit
// loads: lanes 0-15 carry chunks of row 2r, lanes 16-31 of row 2r+1, so a
// warp gathers TWO rows per instruction (9 LDG.256 total, all in flight).
__global__ void __launch_bounds__(32 * WARPS_PER_BLOCK, 1) cbow_main(
    const int*   __restrict__ contexts,   // [B, C]
    const int*   __restrict__ focus,      // [B, K]
    const float* __restrict__ wmask,      // [B, K]
    const float* __restrict__ labels,     // [B, K]
    const float* __restrict__ ctx_emb,    // [VOCAB, DIM]
    const float* __restrict__ neg_emb)    // [VOCAB, DIM]
{
    const int lane = threadIdx.x & 31;
    const int half = lane >> 4;           // 0: even row, 1: odd row
    const int ch   = lane & 15;           // 32B chunk index within row
    const int wid  = threadIdx.x >> 5;
    const int b    = blockIdx.x * WARPS_PER_BLOCK + wid;

    __shared__ float s_row[WARPS_PER_BLOCK];

    // Per-lane index/label staging (lanes < C / < K own one entry each)
    int   ctx_i = (lane < CC) ? contexts[b * CC + lane] : 0;
    int   foc_i = (lane < KK) ? focus[b * KK + lane]    : 0;
    float w     = (lane < KK) ? wmask [b * KK + lane]   : 0.0f;
    float y     = (lane < KK) ? labels[b * KK + lane]   : 0.0f;

    // ---- Issue all 9 row-pair loads up front (MLP=9 x 32B per lane) ----
    F8 cv[CC / 2];                        // 5 ctx row-pairs
#pragma unroll
    for (int r = 0; r < CC / 2; ++r) {
        int row = __shfl_sync(0xffffffffu, ctx_i, 2 * r + half);
        cv[r] = ldg256_persist((const char*)&ctx_emb[(size_t)row * DIM] + ch * 32);
    }
    F8 tv[KK / 2];                        // 4 target row-pairs
#pragma unroll
    for (int r = 0; r < KK / 2; ++r) {
        int row = __shfl_sync(0xffffffffu, foc_i, 2 * r + half);
        tv[r] = ldg256_persist((const char*)&neg_emb[(size_t)row * DIM] + ch * 32);
    }

    // ---- Sum-pool: accumulate my half's rows, then merge halves ----
    float acc[8];
#pragma unroll
    for (int j = 0; j < 8; ++j) acc[j] = cv[0].v[j];
#pragma unroll
    for (int r = 1; r < CC / 2; ++r)
#pragma unroll
        for (int j = 0; j < 8; ++j) acc[j] += cv[r].v[j];
    // lanes l and l+16 hold same dims of different rows -> xor-16 merge
#pragma unroll
    for (int j = 0; j < 8; ++j)
        acc[j] += __shfl_xor_sync(0xffffffffu, acc[j], 16);
    // now every lane holds src dims [8*ch .. 8*ch+8)

    // ---- Dots: per-lane 8-dim partial, reduce within half-warp ----
    float pred_mine = 0.0f;
#pragma unroll
    for (int r = 0; r < KK / 2; ++r) {
        float d = 0.0f;
#pragma unroll
        for (int j = 0; j < 8; ++j) d += acc[j] * tv[r].v[j];
        d += __shfl_xor_sync(0xffffffffu, d, 8);
        d += __shfl_xor_sync(0xffffffffu, d, 4);
        d += __shfl_xor_sync(0xffffffffu, d, 2);
        d += __shfl_xor_sync(0xffffffffu, d, 1);
        // lane 0 holds dot(row 2r), lane 16 holds dot(row 2r+1)
        float d0 = __shfl_sync(0xffffffffu, d, 0);
        float d1 = __shfl_sync(0xffffffffu, d, 16);
        if (lane == 2 * r)     pred_mine = d0;
        if (lane == 2 * r + 1) pred_mine = d1;
    }

    // Lane k (< K) computes its weighted BCE term once
    float bce = 0.0f;
    if (lane < KK) {
        // logaddexp(0, x) = max(x,0) + log1p(exp(-|x|))  (stable softplus)
        float sp = fmaxf(pred_mine, 0.0f) + log1pf(expf(-fabsf(pred_mine)));
        bce = w * (sp - pred_mine * y);
    }

    // num = sum_k bce, den = sum_k w  (w is 0 on lanes >= K)
    float num = bce, den = w;
#pragma unroll
    for (int o = 16; o > 0; o >>= 1) {
        num += __shfl_xor_sync(0xffffffffu, num, o);
        den += __shfl_xor_sync(0xffffffffu, den, o);
    }

    // Per-warp row loss -> per-block partial (fixed order => deterministic)
    if (lane == 0) s_row[wid] = num / den;
    __syncthreads();
    if (threadIdx.x == 0) {
        float acc2 = 0.0f;
#pragma unroll
        for (int i = 0; i < WARPS_PER_BLOCK; ++i) acc2 += s_row[i];
        g_part[blockIdx.x] = acc2;
    }
}

// Stage 2a: 16 blocks x 128 threads, each reduces 128 partials
__global__ void __launch_bounds__(128) cbow_reduce1()
{
    __shared__ float s_acc[4];
    const int tid  = threadIdx.x;
    const int lane = tid & 31;
    const int warp = tid >> 5;

    float v = g_part[blockIdx.x * 128 + tid];
#pragma unroll
    for (int o = 16; o > 0; o >>= 1)
        v += __shfl_xor_sync(0xffffffffu, v, o);
    if (lane == 0) s_acc[warp] = v;
    __syncthreads();

    if (tid == 0)
        g_p2[blockIdx.x] = (double)((s_acc[0] + s_acc[1]) + (s_acc[2] + s_acc[3]));
}

// Stage 2b: one warp finishes 16 partials -> scalar mean
__global__ void __launch_bounds__(32) cbow_reduce2(float* __restrict__ out)
{
    const int lane = threadIdx.x;
    double v = (lane < NP2) ? g_p2[lane] : 0.0;
#pragma unroll
    for (int o = 16; o > 0; o >>= 1)
        v += __shfl_xor_sync(0xffffffffu, v, o);
    if (lane == 0) out[0] = (float)(v / (double)BB);
}

extern "C" void kernel_launch(void* const* d_in, const int* in_sizes, int n_in,
                              void* d_out, int out_size)
{
    const int*   contexts = (const int*)  d_in[0];   // [B, C] int32
    const int*   focus    = (const int*)  d_in[1];   // [B, K] int32
    const float* wmask    = (const float*)d_in[2];   // [B, K] f32
    const float* labels   = (const float*)d_in[3];   // [B, K] f32
    const float* ctx_emb  = (const float*)d_in[4];   // [VOCAB, DIM] f32
    const float* neg_emb  = (const float*)d_in[5];   // [VOCAB, DIM] f32
    float* out = (float*)d_out;

    cbow_main<<<NBLK, 32 * WARPS_PER_BLOCK>>>(
        contexts, focus, wmask, labels, ctx_emb, neg_emb);
    cbow_reduce1<<<NP2, 128>>>();
    cbow_reduce2<<<1, 32>>>(out);
}

// round 15
// speedup vs baseline: 1.0204x; 1.0204x over previous
#include <cuda_runtime.h>
#include <cuda_bf16.h>

// Problem shapes (fixed by the dataset)
#define BB   16384
#define CC   10
#define KK   8
#define DIM  128

#define WARPS_PER_BLOCK 8
#define NBLK (BB / WARPS_PER_BLOCK)   // 2048
#define NP2  16

// Scratch (device globals: allocation-guard-safe)
__device__ float  g_part[NBLK];
__device__ double g_p2[NP2];

// Stage 1 (R4 main, best measured: 18.6us = at the ~4.6TB/s random-gather
// floor). One WARP per example, lane l owns dims [4l..4l+3] as float4.
// All 18 loads in distinct registers (MLP=18); occupancy sacrificed on purpose.
__global__ void __launch_bounds__(32 * WARPS_PER_BLOCK, 1) cbow_main(
    const int*   __restrict__ contexts,   // [B, C]
    const int*   __restrict__ focus,      // [B, K]
    const float* __restrict__ wmask,      // [B, K]
    const float* __restrict__ labels,     // [B, K]
    const float* __restrict__ ctx_emb,    // [VOCAB, DIM]
    const float* __restrict__ neg_emb)    // [VOCAB, DIM]
{
    const int lane = threadIdx.x & 31;
    const int wid  = threadIdx.x >> 5;
    const int b    = blockIdx.x * WARPS_PER_BLOCK + wid;

    __shared__ float s_row[WARPS_PER_BLOCK];

    // Per-lane index/label staging (lanes < C / < K own one entry each)
    int   ctx_i = (lane < CC) ? contexts[b * CC + lane] : 0;
    int   foc_i = (lane < KK) ? focus[b * KK + lane]    : 0;
    float w     = (lane < KK) ? wmask [b * KK + lane]   : 0.0f;
    float y     = (lane < KK) ? labels[b * KK + lane]   : 0.0f;

    // ---- Issue ALL 18 row loads first, into distinct registers ----
    float4 cv[CC];
#pragma unroll
    for (int c = 0; c < CC; ++c) {
        int row = __shfl_sync(0xffffffffu, ctx_i, c);
        cv[c] = __ldg((const float4*)&ctx_emb[(size_t)row * DIM + lane * 4]);
    }
    float4 tv[KK];
#pragma unroll
    for (int k = 0; k < KK; ++k) {
        int row = __shfl_sync(0xffffffffu, foc_i, k);
        tv[k] = __ldg((const float4*)&neg_emb[(size_t)row * DIM + lane * 4]);
    }

    // ---- Sum-pool context embedding ----
    float4 src = cv[0];
#pragma unroll
    for (int c = 1; c < CC; ++c) {
        src.x += cv[c].x; src.y += cv[c].y; src.z += cv[c].z; src.w += cv[c].w;
    }

    // ---- K dot products; butterfly reduce ----
    float pred_mine = 0.0f;
#pragma unroll
    for (int k = 0; k < KK; ++k) {
        float d = src.x * tv[k].x + src.y * tv[k].y
                + src.z * tv[k].z + src.w * tv[k].w;
        d += __shfl_xor_sync(0xffffffffu, d, 16);
        d += __shfl_xor_sync(0xffffffffu, d, 8);
        d += __shfl_xor_sync(0xffffffffu, d, 4);
        d += __shfl_xor_sync(0xffffffffu, d, 2);
        d += __shfl_xor_sync(0xffffffffu, d, 1);
        if (lane == k) pred_mine = d;
    }

    // Lane k (< K) computes its weighted BCE term once
    float bce = 0.0f;
    if (lane < KK) {
        // logaddexp(0, x) = max(x,0) + log1p(exp(-|x|))  (stable softplus)
        float sp = fmaxf(pred_mine, 0.0f) + log1pf(expf(-fabsf(pred_mine)));
        bce = w * (sp - pred_mine * y);
    }

    // num = sum_k bce, den = sum_k w  (w is 0 on lanes >= K)
    float num = bce, den = w;
#pragma unroll
    for (int o = 16; o > 0; o >>= 1) {
        num += __shfl_xor_sync(0xffffffffu, num, o);
        den += __shfl_xor_sync(0xffffffffu, den, o);
    }

    // Per-warp row loss -> per-block partial (fixed order => deterministic)
    if (lane == 0) s_row[wid] = num / den;
    __syncthreads();
    if (threadIdx.x == 0) {
        float acc = 0.0f;
#pragma unroll
        for (int i = 0; i < WARPS_PER_BLOCK; ++i) acc += s_row[i];
        g_part[blockIdx.x] = acc;
    }
}

// Stage 2a: 16 blocks x 128 threads, each reduces 128 partials
// (two-kernel tail measured at ~1.7us total in R7; grid=1 reduces cost 6+us)
__global__ void __launch_bounds__(128) cbow_reduce1()
{
    __shared__ float s_acc[4];
    const int tid  = threadIdx.x;
    const int lane = tid & 31;
    const int warp = tid >> 5;

    float v = g_part[blockIdx.x * 128 + tid];
#pragma unroll
    for (int o = 16; o > 0; o >>= 1)
        v += __shfl_xor_sync(0xffffffffu, v, o);
    if (lane == 0) s_acc[warp] = v;
    __syncthreads();

    if (tid == 0)
        g_p2[blockIdx.x] = (double)((s_acc[0] + s_acc[1]) + (s_acc[2] + s_acc[3]));
}

// Stage 2b: one warp finishes 16 partials -> scalar mean
__global__ void __launch_bounds__(32) cbow_reduce2(float* __restrict__ out)
{
    const int lane = threadIdx.x;
    double v = (lane < NP2) ? g_p2[lane] : 0.0;
#pragma unroll
    for (int o = 16; o > 0; o >>= 1)
        v += __shfl_xor_sync(0xffffffffu, v, o);
    if (lane == 0) out[0] = (float)(v / (double)BB);
}

extern "C" void kernel_launch(void* const* d_in, const int* in_sizes, int n_in,
                              void* d_out, int out_size)
{
    const int*   contexts = (const int*)  d_in[0];   // [B, C] int32
    const int*   focus    = (const int*)  d_in[1];   // [B, K] int32
    const float* wmask    = (const float*)d_in[2];   // [B, K] f32
    const float* labels   = (const float*)d_in[3];   // [B, K] f32
    const float* ctx_emb  = (const float*)d_in[4];   // [VOCAB, DIM] f32
    const float* neg_emb  = (const float*)d_in[5];   // [VOCAB, DIM] f32
    float* out = (float*)d_out;

    cbow_main<<<NBLK, 32 * WARPS_PER_BLOCK>>>(
        contexts, focus, wmask, labels, ctx_emb, neg_emb);
    cbow_reduce1<<<NP2, 128>>>();
    cbow_reduce2<<<1, 32>>>(out);
}